// round 5
// baseline (speedup 1.0000x reference)
#include <cuda_runtime.h>
#include <math.h>
#include <stdint.h>

#define BATCH 64
#define EDIM 1024
#define HDIM 1024
#define FDIM 2048
#define VDIM 32000
#define NLAYER 8
#define BH (BATCH * HDIM)

// ---------------- scratch (no allocation allowed) ----------------
__device__ __align__(16) float g_xe[BATCH * EDIM];
__device__ __align__(16) float g_attn[BATCH * HDIM];
__device__ __align__(16) float g_buf0[BATCH * HDIM];
__device__ __align__(16) float g_buf1[BATCH * HDIM];
__device__ __align__(16) float g_gh[NLAYER * BATCH * 3 * HDIM];
__device__ int g_bar[NLAYER];    // gru chain barriers
__device__ int g_bar2[4];        // attn chain barriers

// ---------------- ptx helpers ----------------
__device__ __forceinline__ uint32_t tfb(float x) { return __float_as_uint(x); }

__device__ __forceinline__ void cp16(uint32_t saddr, const void* g) {
    asm volatile("cp.async.cg.shared.global [%0], [%1], 16;\n" ::"r"(saddr), "l"(g));
}
__device__ __forceinline__ void cp_commit() { asm volatile("cp.async.commit_group;\n"); }
template <int N>
__device__ __forceinline__ void cp_wait() { asm volatile("cp.async.wait_group %0;\n" ::"n"(N)); }

__device__ __forceinline__ void mma8(float* c, uint32_t a0, uint32_t a1, uint32_t a2,
                                     uint32_t a3, uint32_t b0, uint32_t b1) {
    asm volatile(
        "mma.sync.aligned.m16n8k8.row.col.f32.tf32.tf32.f32 "
        "{%0,%1,%2,%3}, {%4,%5,%6,%7}, {%8,%9}, {%0,%1,%2,%3};\n"
        : "+f"(c[0]), "+f"(c[1]), "+f"(c[2]), "+f"(c[3])
        : "r"(a0), "r"(a1), "r"(a2), "r"(a3), "r"(b0), "r"(b1));
}

// ---------------- embed + barrier init ----------------
__global__ void embed_relu_kernel(const float* __restrict__ emb,
                                  const int* __restrict__ x,
                                  float* __restrict__ xe) {
    if (blockIdx.x == 0) {
        if (threadIdx.x < NLAYER) g_bar[threadIdx.x] = 0;
        else if (threadIdx.x < NLAYER + 4) g_bar2[threadIdx.x - NLAYER] = 0;
    }
    const int b = blockIdx.x;
    const int row = x[b];
    const float* src = emb + (size_t)row * EDIM;
    float* dst = xe + (size_t)b * EDIM;
    for (int e = threadIdx.x; e < EDIM; e += blockDim.x) {
        float v = src[e];
        dst[e] = v > 0.f ? v : 0.f;
    }
}

// ---------------- persistent attention chain (4 layers, 64 blocks) ----------------
// L0: buf0 = relu(feature@mapW^T+mapb) + attention   (K=2048)
// L1: buf1 = relu(buf0@aiW^T+aib)
// L2: buf0 = relu(buf1@ahW^T+ahb)
// L3: attn = relu(buf0@aoW^T+aob)
__global__ __launch_bounds__(256) void attn_chain(
    const float* __restrict__ feature, const float* __restrict__ attention,
    const float* __restrict__ mapW, const float* __restrict__ mapb,
    const float* __restrict__ aiW, const float* __restrict__ aib,
    const float* __restrict__ ahW, const float* __restrict__ ahb,
    const float* __restrict__ aoW, const float* __restrict__ aob,
    float* __restrict__ buf0, float* __restrict__ buf1, float* __restrict__ attnOut) {
    constexpr int S = 3, LDT = 36, BN = 16;
    __shared__ float As[S * 64 * LDT];
    __shared__ float Ws[S * BN * LDT];

    const float* Aptr[4] = {feature, buf0, buf1, buf0};
    const float* Wptr[4] = {mapW, aiW, ahW, aoW};
    const float* bptr[4] = {mapb, aib, ahb, aob};
    float* optr[4] = {buf0, buf1, buf0, attnOut};
    const int Ks[4] = {FDIM, HDIM, HDIM, HDIM};

    const int tid = threadIdx.x, lane = tid & 31, warp = tid >> 5;
    const int wm = warp & 3, wn = warp >> 2;  // wn in {0,1}
    const int r = lane >> 2, kk = lane & 3;
    const int nBlock = blockIdx.x * BN;

    const uint32_t sA = (uint32_t)__cvta_generic_to_shared(As);
    const uint32_t sW = (uint32_t)__cvta_generic_to_shared(Ws);

    for (int layer = 0; layer < 4; layer++) {
        const float* A = Aptr[layer];
        const float* W = Wptr[layer];
        const int K = Ks[layer];
        const int nK = K / 32;

        auto issue = [&](int st, int k0) {
#pragma unroll
            for (int t = 0; t < 2; t++) {
                const int idx = tid + t * 256;  // < 512
                const int m = idx >> 3, k4 = idx & 7;
                cp16(sA + (uint32_t)(((st * 64 + m) * LDT + k4 * 4) * 4),
                     A + (size_t)m * K + k0 + k4 * 4);
            }
            if (tid < BN * 8) {
                const int wr = tid >> 3, k4 = tid & 7;
                cp16(sW + (uint32_t)(((st * BN + wr) * LDT + k4 * 4) * 4),
                     W + (size_t)(nBlock + wr) * K + k0 + k4 * 4);
            }
        };

#pragma unroll
        for (int p = 0; p < S - 1; p++) {
            if (p < nK) issue(p, p * 32);
            cp_commit();
        }

        float acc[4] = {0.f, 0.f, 0.f, 0.f};
        for (int kt = 0; kt < nK; kt++) {
            cp_wait<S - 2>();
            __syncthreads();
            const int pf = kt + S - 1;
            if (pf < nK) issue(pf % S, pf * 32);
            cp_commit();
            const float* a_ = As + (kt % S) * 64 * LDT;
            const float* w_ = Ws + (kt % S) * BN * LDT;
#pragma unroll
            for (int s = 0; s < 4; s++) {
                const int col = s * 8 + kk;
                const uint32_t a0 = tfb(a_[(wm * 16 + r) * LDT + col]);
                const uint32_t a1 = tfb(a_[(wm * 16 + r + 8) * LDT + col]);
                const uint32_t a2 = tfb(a_[(wm * 16 + r) * LDT + col + 4]);
                const uint32_t a3 = tfb(a_[(wm * 16 + r + 8) * LDT + col + 4]);
                const int n = wn * 8 + r;
                mma8(acc, a0, a1, a2, a3, tfb(w_[n * LDT + col]),
                     tfb(w_[n * LDT + col + 4]));
            }
        }
        cp_wait<0>();

        // epilogue: bias + relu (+attention on layer 0)
        const int row0 = wm * 16 + r;
        const int col = nBlock + wn * 8 + 2 * kk;
        const float b0v = bptr[layer][col], b1v = bptr[layer][col + 1];
        float v0 = fmaxf(acc[0] + b0v, 0.f), v1 = fmaxf(acc[1] + b1v, 0.f);
        float v2 = fmaxf(acc[2] + b0v, 0.f), v3 = fmaxf(acc[3] + b1v, 0.f);
        if (layer == 0) {
            v0 += attention[(size_t)row0 * HDIM + col];
            v1 += attention[(size_t)row0 * HDIM + col + 1];
            v2 += attention[(size_t)(row0 + 8) * HDIM + col];
            v3 += attention[(size_t)(row0 + 8) * HDIM + col + 1];
        }
        float* o = optr[layer];
        *reinterpret_cast<float2*>(o + (size_t)row0 * HDIM + col) = make_float2(v0, v1);
        *reinterpret_cast<float2*>(o + (size_t)(row0 + 8) * HDIM + col) = make_float2(v2, v3);

        if (layer < 3) {
            __threadfence();
            __syncthreads();
            if (tid == 0) {
                atomicAdd(&g_bar2[layer], 1);
                while (atomicAdd(&g_bar2[layer], 0) < (int)gridDim.x) __nanosleep(32);
            }
            __syncthreads();
        }
    }
}

// ---------------- pipelined tf32 GEMM: C[64,N] = (A (+A2)) @ W^T + bias ----------------
template <int BN, bool A2F>
__global__ __launch_bounds__(256) void gemm_pipe(
    const float* __restrict__ A, const float* __restrict__ A2,
    const float* __restrict__ W, const float* __restrict__ bias,
    float* __restrict__ out, int K, int N, int strideA, int strideA2) {
    constexpr int S = 3;
    constexpr int LDT = 36;
    constexpr int NT = BN / 16;
    extern __shared__ float sm[];
    float* As = sm;
    float* Ws = sm + S * 64 * LDT;
    float* As2 = Ws + S * BN * LDT;  // only if A2F

    const int y = blockIdx.y;
    A += (size_t)y * strideA;
    if (A2F) A2 += (size_t)y * strideA2;
    W += (size_t)y * N * K;
    bias += (size_t)y * N;
    out += (size_t)y * BATCH * N;

    const int tid = threadIdx.x, lane = tid & 31, warp = tid >> 5;
    const int wm = warp & 3, wn = warp >> 2;
    const int nBlock = blockIdx.x * BN;
    const int r = lane >> 2, kk = lane & 3;

    const uint32_t sA = (uint32_t)__cvta_generic_to_shared(As);
    const uint32_t sW = (uint32_t)__cvta_generic_to_shared(Ws);
    const uint32_t sA2 = (uint32_t)__cvta_generic_to_shared(As2);

    auto issue = [&](int st, int k0) {
#pragma unroll
        for (int t = 0; t < 2; t++) {
            const int idx = tid + t * 256;
            const int m = idx >> 3, k4 = idx & 7;
            const uint32_t off = (uint32_t)(((st * 64 + m) * LDT + k4 * 4) * 4);
            cp16(sA + off, A + (size_t)m * K + k0 + k4 * 4);
            if (A2F) cp16(sA2 + off, A2 + (size_t)m * K + k0 + k4 * 4);
        }
        for (int idx = tid; idx < BN * 8; idx += 256) {
            const int n = idx >> 3, k4 = idx & 7;
            cp16(sW + (uint32_t)(((st * BN + n) * LDT + k4 * 4) * 4),
                 W + (size_t)(nBlock + n) * K + k0 + k4 * 4);
        }
    };

    const int nK = K / 32;
#pragma unroll
    for (int p = 0; p < S - 1; p++) {
        if (p < nK) issue(p, p * 32);
        cp_commit();
    }

    float acc[NT][4];
#pragma unroll
    for (int i = 0; i < NT; i++)
#pragma unroll
        for (int j = 0; j < 4; j++) acc[i][j] = 0.f;

    for (int kt = 0; kt < nK; kt++) {
        cp_wait<S - 2>();
        __syncthreads();
        const int pf = kt + S - 1;
        if (pf < nK) issue(pf % S, pf * 32);
        cp_commit();
        const float* a_ = As + (kt % S) * 64 * LDT;
        const float* a2_ = As2 + (kt % S) * 64 * LDT;
        const float* w_ = Ws + (kt % S) * BN * LDT;
#pragma unroll
        for (int s = 0; s < 4; s++) {
            const int col = s * 8 + kk;
            float f0 = a_[(wm * 16 + r) * LDT + col];
            float f1 = a_[(wm * 16 + r + 8) * LDT + col];
            float f2 = a_[(wm * 16 + r) * LDT + col + 4];
            float f3 = a_[(wm * 16 + r + 8) * LDT + col + 4];
            if (A2F) {
                f0 += a2_[(wm * 16 + r) * LDT + col];
                f1 += a2_[(wm * 16 + r + 8) * LDT + col];
                f2 += a2_[(wm * 16 + r) * LDT + col + 4];
                f3 += a2_[(wm * 16 + r + 8) * LDT + col + 4];
            }
            const uint32_t a0 = tfb(f0), a1 = tfb(f1), a2v = tfb(f2), a3 = tfb(f3);
#pragma unroll
            for (int nt = 0; nt < NT; nt++) {
                const int n = wn * (BN / 2) + nt * 8 + r;
                mma8(acc[nt], a0, a1, a2v, a3, tfb(w_[n * LDT + col]),
                     tfb(w_[n * LDT + col + 4]));
            }
        }
    }

    const int row0 = wm * 16 + r;
#pragma unroll
    for (int nt = 0; nt < NT; nt++) {
        const int col = nBlock + wn * (BN / 2) + nt * 8 + 2 * kk;
        const float b0v = bias[col], b1v = bias[col + 1];
        *reinterpret_cast<float2*>(out + (size_t)row0 * N + col) =
            make_float2(acc[nt][0] + b0v, acc[nt][1] + b1v);
        *reinterpret_cast<float2*>(out + (size_t)(row0 + 8) * N + col) =
            make_float2(acc[nt][2] + b0v, acc[nt][3] + b1v);
    }
}

// ---------------- persistent fused GRU chain ----------------
__global__ __launch_bounds__(384) void gru_chain(
    const float* __restrict__ xe, float* __restrict__ nh, float* __restrict__ h1,
    const float* __restrict__ gru_Wih, const float* __restrict__ gru_bih,
    const float* __restrict__ gh, const float* __restrict__ hiddens,
    const float* __restrict__ attn) {
    constexpr int S = 3;
    constexpr int LDT = 36;
    constexpr int K = EDIM;
    extern __shared__ float sm[];
    float* As = sm;
    float* Wsf = As + S * 64 * LDT;
    float* As2 = Wsf + S * 24 * LDT;
    float* Cs = As2 + S * 64 * LDT;

    const int h0 = blockIdx.x * 8;
    const int tid = threadIdx.x, lane = tid & 31, warp = tid >> 5;
    const int wm = warp & 3, sec = warp >> 2;
    const int r = lane >> 2, kk = lane & 3;

    const uint32_t sA = (uint32_t)__cvta_generic_to_shared(As);
    const uint32_t sW = (uint32_t)__cvta_generic_to_shared(Wsf);
    const uint32_t sA2 = (uint32_t)__cvta_generic_to_shared(As2);

    for (int layer = 0; layer < NLAYER; layer++) {
        const float* A;
        const float* A2 = nullptr;
        switch (layer) {
            case 0: A = xe; break;
            case 1: A = nh; break;
            case 2: A = nh + BH; break;
            case 3: A = nh + BH;     A2 = nh + 2 * BH; break;
            case 4: A = nh + 2 * BH; A2 = nh + 3 * BH; break;
            case 5: A = nh + 3 * BH; A2 = nh + 4 * BH; break;
            case 6: A = nh + 4 * BH; A2 = nh + 5 * BH; break;
            default: A = nh + 5 * BH; A2 = nh + 6 * BH; break;
        }
        const bool has2 = (A2 != nullptr);
        const float* Wih = gru_Wih + (size_t)layer * 3 * HDIM * K;
        const float* bih = gru_bih + (size_t)layer * 3 * HDIM;
        const float* ghL = gh + (size_t)layer * BATCH * 3 * HDIM;
        const float* hidL = hiddens + (size_t)layer * BH;
        float* outh = nh + (size_t)layer * BH;

        auto issue = [&](int st, int k0) {
            for (int idx = tid; idx < 512; idx += 384) {
                const int m = idx >> 3, k4 = idx & 7;
                const uint32_t off = (uint32_t)(((st * 64 + m) * LDT + k4 * 4) * 4);
                cp16(sA + off, A + (size_t)m * K + k0 + k4 * 4);
                if (has2) cp16(sA2 + off, A2 + (size_t)m * K + k0 + k4 * 4);
            }
            if (tid < 192) {
                const int wr = tid >> 3, k4 = tid & 7;
                const int grow = (wr >> 3) * HDIM + h0 + (wr & 7);
                cp16(sW + (uint32_t)(((st * 24 + wr) * LDT + k4 * 4) * 4),
                     Wih + (size_t)grow * K + k0 + k4 * 4);
            }
        };

        const int nK = K / 32;
#pragma unroll
        for (int p = 0; p < S - 1; p++) { issue(p, p * 32); cp_commit(); }

        float acc[4] = {0.f, 0.f, 0.f, 0.f};
        for (int kt = 0; kt < nK; kt++) {
            cp_wait<S - 2>();
            __syncthreads();
            const int pf = kt + S - 1;
            if (pf < nK) issue(pf % S, pf * 32);
            cp_commit();
            const float* a_ = As + (kt % S) * 64 * LDT;
            const float* a2_ = As2 + (kt % S) * 64 * LDT;
            const float* w_ = Wsf + (kt % S) * 24 * LDT;
#pragma unroll
            for (int s = 0; s < 4; s++) {
                const int col = s * 8 + kk;
                float f0 = a_[(wm * 16 + r) * LDT + col];
                float f1 = a_[(wm * 16 + r + 8) * LDT + col];
                float f2 = a_[(wm * 16 + r) * LDT + col + 4];
                float f3 = a_[(wm * 16 + r + 8) * LDT + col + 4];
                if (has2) {
                    f0 += a2_[(wm * 16 + r) * LDT + col];
                    f1 += a2_[(wm * 16 + r + 8) * LDT + col];
                    f2 += a2_[(wm * 16 + r) * LDT + col + 4];
                    f3 += a2_[(wm * 16 + r + 8) * LDT + col + 4];
                }
                mma8(acc, tfb(f0), tfb(f1), tfb(f2), tfb(f3),
                     tfb(w_[(sec * 8 + r) * LDT + col]),
                     tfb(w_[(sec * 8 + r) * LDT + col + 4]));
            }
        }
        cp_wait<0>();

        const int row0 = wm * 16 + r;
        *reinterpret_cast<float2*>(&Cs[row0 * 26 + sec * 8 + 2 * kk]) =
            make_float2(acc[0], acc[1]);
        *reinterpret_cast<float2*>(&Cs[(row0 + 8) * 26 + sec * 8 + 2 * kk]) =
            make_float2(acc[2], acc[3]);
        __syncthreads();

        for (int idx = tid; idx < 512; idx += 384) {
            const int b = idx >> 3, hh = idx & 7;
            const int h = h0 + hh;
            const float ir = Cs[b * 26 + hh] + bih[h];
            const float iz = Cs[b * 26 + 8 + hh] + bih[HDIM + h];
            const float in_ = Cs[b * 26 + 16 + hh] + bih[2 * HDIM + h];
            const float* ghb = ghL + (size_t)b * 3 * HDIM + h;
            const float rr = 1.f / (1.f + expf(-(ir + ghb[0])));
            const float zz = 1.f / (1.f + expf(-(iz + ghb[HDIM])));
            const float nn = tanhf(in_ + rr * ghb[2 * HDIM]);
            const float hp = hidL[(size_t)b * HDIM + h] + attn[(size_t)b * HDIM + h];
            const float o = (1.f - zz) * nn + zz * hp;
            outh[(size_t)b * HDIM + h] = o;
            if (layer == 0) h1[(size_t)b * HDIM + h] = o;
        }

        if (layer < NLAYER - 1) {
            __threadfence();
            __syncthreads();
            if (tid == 0) {
                atomicAdd(&g_bar[layer], 1);
                while (atomicAdd(&g_bar[layer], 0) < (int)gridDim.x) __nanosleep(32);
            }
            __syncthreads();
        }
    }
}

// ---------------- 2-pass online log_softmax ----------------
__global__ __launch_bounds__(1024) void log_softmax_kernel(float* __restrict__ logits) {
    const int b = blockIdx.x;
    float* row = logits + (size_t)b * VDIM;
    __shared__ float smax[32], ssum[32];
    __shared__ float s_lse;
    const int lane = threadIdx.x & 31;
    const int wid = threadIdx.x >> 5;

    float m = -1e30f, s = 0.f;
    const float4* r4 = reinterpret_cast<const float4*>(row);
    for (int v = threadIdx.x; v < VDIM / 4; v += blockDim.x) {
        float4 x = r4[v];
#define ONE(val) { float d = (val) - m; \
        if (d > 0.f) { s = s * __expf(-d) + 1.f; m = (val); } else s += __expf(d); }
        ONE(x.x) ONE(x.y) ONE(x.z) ONE(x.w)
#undef ONE
    }
#pragma unroll
    for (int o = 16; o; o >>= 1) {
        float mo = __shfl_xor_sync(0xffffffffu, m, o);
        float so = __shfl_xor_sync(0xffffffffu, s, o);
        float mn = fmaxf(m, mo);
        s = s * __expf(m - mn) + so * __expf(mo - mn);
        m = mn;
    }
    if (lane == 0) { smax[wid] = m; ssum[wid] = s; }
    __syncthreads();
    if (wid == 0) {
        float mm = (lane < (blockDim.x >> 5)) ? smax[lane] : -1e30f;
        float ss = (lane < (blockDim.x >> 5)) ? ssum[lane] : 0.f;
#pragma unroll
        for (int o = 16; o; o >>= 1) {
            float mo = __shfl_xor_sync(0xffffffffu, mm, o);
            float so = __shfl_xor_sync(0xffffffffu, ss, o);
            float mn = fmaxf(mm, mo);
            ss = ss * __expf(mm - mn) + so * __expf(mo - mn);
            mm = mn;
        }
        if (lane == 0) s_lse = mm + logf(ss);
    }
    __syncthreads();
    const float lse = s_lse;
    float4* w4 = reinterpret_cast<float4*>(row);
    for (int v = threadIdx.x; v < VDIM / 4; v += blockDim.x) {
        float4 x = w4[v];
        x.x -= lse; x.y -= lse; x.z -= lse; x.w -= lse;
        w4[v] = x;
    }
}

// ---------------- launch ----------------
extern "C" void kernel_launch(void* const* d_in, const int* in_sizes, int n_in,
                              void* d_out, int out_size) {
    const float* feature   = (const float*)d_in[0];
    const int*   x         = (const int*)d_in[1];
    const float* attention = (const float*)d_in[2];
    const float* hiddens   = (const float*)d_in[3];
    const float* emb       = (const float*)d_in[4];
    const float* map_W     = (const float*)d_in[5];
    const float* map_b     = (const float*)d_in[6];
    const float* ai_W      = (const float*)d_in[7];
    const float* ai_b      = (const float*)d_in[8];
    const float* ah_W      = (const float*)d_in[9];
    const float* ah_b      = (const float*)d_in[10];
    const float* ao_W      = (const float*)d_in[11];
    const float* ao_b      = (const float*)d_in[12];
    const float* gru_Wih   = (const float*)d_in[13];
    const float* gru_Whh   = (const float*)d_in[14];
    const float* gru_bih   = (const float*)d_in[15];
    const float* gru_bhh   = (const float*)d_in[16];
    const float* out_W     = (const float*)d_in[17];
    const float* out_b     = (const float*)d_in[18];

    float* out = (float*)d_out;
    float* logp = out;
    float* h1   = out + (size_t)BATCH * VDIM;
    float* nh   = h1 + (size_t)BATCH * HDIM;

    float *xe, *attn, *buf0, *buf1, *gh;
    cudaGetSymbolAddress((void**)&xe, g_xe);
    cudaGetSymbolAddress((void**)&attn, g_attn);
    cudaGetSymbolAddress((void**)&buf0, g_buf0);
    cudaGetSymbolAddress((void**)&buf1, g_buf1);
    cudaGetSymbolAddress((void**)&gh, g_gh);

    const int SM_G32A2 = (3 * 64 * 36 * 2 + 3 * 32 * 36) * 4;                 // 69120
    const int SM_G64   = (3 * 64 * 36 * 2) * 4;                               // 55296
    const int SM_CH    = (3 * 64 * 36 + 3 * 24 * 36 + 3 * 64 * 36) * 4 + 64 * 26 * 4;
    cudaFuncSetAttribute((const void*)gemm_pipe<32, true>,
                         cudaFuncAttributeMaxDynamicSharedMemorySize, SM_G32A2);
    cudaFuncSetAttribute((const void*)gemm_pipe<64, false>,
                         cudaFuncAttributeMaxDynamicSharedMemorySize, SM_G64);
    cudaFuncSetAttribute((const void*)gru_chain,
                         cudaFuncAttributeMaxDynamicSharedMemorySize, SM_CH);

    // 1) embed (+ barrier init)
    embed_relu_kernel<<<BATCH, 256>>>(emb, x, xe);

    // 2) persistent attention chain (4 layers, 1 launch)
    attn_chain<<<HDIM / 16, 256>>>(feature, attention, map_W, map_b, ai_W, ai_b,
                                   ah_W, ah_b, ao_W, ao_b, buf0, buf1, attn);

    // 3) all 8 gh GEMMs, one batched launch: gh[l] = (hiddens[l]+attn) @ Whh[l]^T + bhh[l]
    gemm_pipe<32, true><<<dim3(3 * HDIM / 32, NLAYER, 1), 256, SM_G32A2>>>(
        hiddens, attn, gru_Whh, gru_bhh, gh, HDIM, 3 * HDIM, BH, 0);

    // 4) fused persistent GRU chain (all 8 layers, 1 launch)
    gru_chain<<<HDIM / 8, 384, SM_CH>>>(xe, nh, h1, gru_Wih, gru_bih, gh,
                                        hiddens, attn);

    // 5) output projection + log-softmax
    gemm_pipe<64, false><<<dim3(VDIM / 64, 1, 1), 256, SM_G64>>>(
        nh + 7 * (size_t)BH, nullptr, out_W, out_b, logp, HDIM, VDIM, 0, 0);
    log_softmax_kernel<<<BATCH, 1024>>>(logp);
}

// round 6
// speedup vs baseline: 1.1748x; 1.1748x over previous
#include <cuda_runtime.h>
#include <math.h>
#include <stdint.h>

#define BATCH 64
#define EDIM 1024
#define HDIM 1024
#define FDIM 2048
#define VDIM 32000
#define NLAYER 8
#define BH (BATCH * HDIM)

// ---------------- scratch (no allocation allowed) ----------------
__device__ __align__(16) float g_xe[BATCH * EDIM];
__device__ __align__(16) float g_buf0[BATCH * HDIM];
__device__ __align__(16) float g_buf1[BATCH * HDIM];
__device__ __align__(16) float g_gh[NLAYER * BATCH * 3 * HDIM];
__device__ __align__(16) float g_hplus[NLAYER * BATCH * HDIM];
__device__ __align__(16) float g_sum0[BATCH * HDIM];
__device__ __align__(16) float g_sum1[BATCH * HDIM];
__device__ int g_bar[NLAYER];    // gru chain barriers
__device__ int g_bar2[4];        // attn chain barriers

// ---------------- ptx helpers ----------------
__device__ __forceinline__ uint32_t tfb(float x) { return __float_as_uint(x); }

__device__ __forceinline__ void cp16(uint32_t saddr, const void* g) {
    asm volatile("cp.async.cg.shared.global [%0], [%1], 16;\n" ::"r"(saddr), "l"(g));
}
__device__ __forceinline__ void cp_commit() { asm volatile("cp.async.commit_group;\n"); }
template <int N>
__device__ __forceinline__ void cp_wait() { asm volatile("cp.async.wait_group %0;\n" ::"n"(N)); }

__device__ __forceinline__ void mma8(float* c, uint32_t a0, uint32_t a1, uint32_t a2,
                                     uint32_t a3, uint32_t b0, uint32_t b1) {
    asm volatile(
        "mma.sync.aligned.m16n8k8.row.col.f32.tf32.tf32.f32 "
        "{%0,%1,%2,%3}, {%4,%5,%6,%7}, {%8,%9}, {%0,%1,%2,%3};\n"
        : "+f"(c[0]), "+f"(c[1]), "+f"(c[2]), "+f"(c[3])
        : "r"(a0), "r"(a1), "r"(a2), "r"(a3), "r"(b0), "r"(b1));
}

// ---------------- embed + barrier init ----------------
__global__ void embed_relu_kernel(const float* __restrict__ emb,
                                  const int* __restrict__ x,
                                  float* __restrict__ xe) {
    if (blockIdx.x == 0) {
        if (threadIdx.x < NLAYER) g_bar[threadIdx.x] = 0;
        else if (threadIdx.x < NLAYER + 4) g_bar2[threadIdx.x - NLAYER] = 0;
    }
    const int b = blockIdx.x;
    const int row = x[b];
    const float* src = emb + (size_t)row * EDIM;
    float* dst = xe + (size_t)b * EDIM;
    for (int e = threadIdx.x; e < EDIM; e += blockDim.x) {
        float v = src[e];
        dst[e] = v > 0.f ? v : 0.f;
    }
}

// ---------------- persistent attention chain (4 layers, 64 blocks) ----------------
// L0: buf0 = relu(feature@mapW^T+mapb) + attention   (K=2048)
// L1: buf1 = relu(buf0@aiW^T+aib)
// L2: buf0 = relu(buf1@ahW^T+ahb)
// L3: attn = relu(buf0@aoW^T+aob); epilogue writes hplus[l] = hiddens[l] + attn
__global__ __launch_bounds__(256) void attn_chain(
    const float* __restrict__ feature, const float* __restrict__ attention,
    const float* __restrict__ mapW, const float* __restrict__ mapb,
    const float* __restrict__ aiW, const float* __restrict__ aib,
    const float* __restrict__ ahW, const float* __restrict__ ahb,
    const float* __restrict__ aoW, const float* __restrict__ aob,
    float* __restrict__ buf0, float* __restrict__ buf1,
    const float* __restrict__ hiddens, float* __restrict__ hplus) {
    constexpr int S = 3, LDT = 36, BN = 16;
    __shared__ float As[S * 64 * LDT];
    __shared__ float Ws[S * BN * LDT];

    const float* Aptr[4] = {feature, buf0, buf1, buf0};
    const float* Wptr[4] = {mapW, aiW, ahW, aoW};
    const float* bptr[4] = {mapb, aib, ahb, aob};
    float* optr[3] = {buf0, buf1, buf0};
    const int Ks[4] = {FDIM, HDIM, HDIM, HDIM};

    const int tid = threadIdx.x, lane = tid & 31, warp = tid >> 5;
    const int wm = warp & 3, wn = warp >> 2;
    const int r = lane >> 2, kk = lane & 3;
    const int nBlock = blockIdx.x * BN;

    const uint32_t sA = (uint32_t)__cvta_generic_to_shared(As);
    const uint32_t sW = (uint32_t)__cvta_generic_to_shared(Ws);

    for (int layer = 0; layer < 4; layer++) {
        const float* A = Aptr[layer];
        const float* W = Wptr[layer];
        const int K = Ks[layer];
        const int nK = K / 32;

        auto issue = [&](int st, int k0) {
#pragma unroll
            for (int t = 0; t < 2; t++) {
                const int idx = tid + t * 256;
                const int m = idx >> 3, k4 = idx & 7;
                cp16(sA + (uint32_t)(((st * 64 + m) * LDT + k4 * 4) * 4),
                     A + (size_t)m * K + k0 + k4 * 4);
            }
            if (tid < BN * 8) {
                const int wr = tid >> 3, k4 = tid & 7;
                cp16(sW + (uint32_t)(((st * BN + wr) * LDT + k4 * 4) * 4),
                     W + (size_t)(nBlock + wr) * K + k0 + k4 * 4);
            }
        };

#pragma unroll
        for (int p = 0; p < S - 1; p++) {
            if (p < nK) issue(p, p * 32);
            cp_commit();
        }

        float acc[4] = {0.f, 0.f, 0.f, 0.f};
        for (int kt = 0; kt < nK; kt++) {
            cp_wait<S - 2>();
            __syncthreads();
            const int pf = kt + S - 1;
            if (pf < nK) issue(pf % S, pf * 32);
            cp_commit();
            const float* a_ = As + (kt % S) * 64 * LDT;
            const float* w_ = Ws + (kt % S) * BN * LDT;
#pragma unroll
            for (int s = 0; s < 4; s++) {
                const int col = s * 8 + kk;
                const uint32_t a0 = tfb(a_[(wm * 16 + r) * LDT + col]);
                const uint32_t a1 = tfb(a_[(wm * 16 + r + 8) * LDT + col]);
                const uint32_t a2 = tfb(a_[(wm * 16 + r) * LDT + col + 4]);
                const uint32_t a3 = tfb(a_[(wm * 16 + r + 8) * LDT + col + 4]);
                const int n = wn * 8 + r;
                mma8(acc, a0, a1, a2, a3, tfb(w_[n * LDT + col]),
                     tfb(w_[n * LDT + col + 4]));
            }
        }
        cp_wait<0>();

        const int row0 = wm * 16 + r;
        const int col = nBlock + wn * 8 + 2 * kk;
        const float b0v = bptr[layer][col], b1v = bptr[layer][col + 1];
        float v0 = fmaxf(acc[0] + b0v, 0.f), v1 = fmaxf(acc[1] + b1v, 0.f);
        float v2 = fmaxf(acc[2] + b0v, 0.f), v3 = fmaxf(acc[3] + b1v, 0.f);
        if (layer == 0) {
            v0 += attention[(size_t)row0 * HDIM + col];
            v1 += attention[(size_t)row0 * HDIM + col + 1];
            v2 += attention[(size_t)(row0 + 8) * HDIM + col];
            v3 += attention[(size_t)(row0 + 8) * HDIM + col + 1];
        }
        if (layer < 3) {
            float* o = optr[layer];
            *reinterpret_cast<float2*>(o + (size_t)row0 * HDIM + col) = make_float2(v0, v1);
            *reinterpret_cast<float2*>(o + (size_t)(row0 + 8) * HDIM + col) = make_float2(v2, v3);
        } else {
            // hplus[l] = hiddens[l] + attn  for all 8 layers
#pragma unroll
            for (int l = 0; l < NLAYER; l++) {
                const size_t b0i = (size_t)l * BH + (size_t)row0 * HDIM + col;
                const size_t b1i = (size_t)l * BH + (size_t)(row0 + 8) * HDIM + col;
                float2 h0 = *reinterpret_cast<const float2*>(hiddens + b0i);
                float2 h8 = *reinterpret_cast<const float2*>(hiddens + b1i);
                *reinterpret_cast<float2*>(hplus + b0i) = make_float2(h0.x + v0, h0.y + v1);
                *reinterpret_cast<float2*>(hplus + b1i) = make_float2(h8.x + v2, h8.y + v3);
            }
        }

        if (layer < 3) {
            __threadfence();
            __syncthreads();
            if (tid == 0) {
                atomicAdd(&g_bar2[layer], 1);
                while (atomicAdd(&g_bar2[layer], 0) < (int)gridDim.x) __nanosleep(32);
            }
            __syncthreads();
        }
    }
}

// ---------------- pipelined tf32 GEMM: C[64,N] = A @ W^T + bias ----------------
template <int BN>
__global__ __launch_bounds__(256) void gemm_pipe(
    const float* __restrict__ A, const float* __restrict__ W,
    const float* __restrict__ bias, float* __restrict__ out,
    int K, int N, int strideA) {
    constexpr int S = 3;
    constexpr int LDT = 36;
    constexpr int NT = BN / 16;
    extern __shared__ float sm[];
    float* As = sm;
    float* Ws = sm + S * 64 * LDT;

    const int y = blockIdx.y;
    A += (size_t)y * strideA;
    W += (size_t)y * N * K;
    bias += (size_t)y * N;
    out += (size_t)y * BATCH * N;

    const int tid = threadIdx.x, lane = tid & 31, warp = tid >> 5;
    const int wm = warp & 3, wn = warp >> 2;
    const int nBlock = blockIdx.x * BN;
    const int r = lane >> 2, kk = lane & 3;

    const uint32_t sA = (uint32_t)__cvta_generic_to_shared(As);
    const uint32_t sW = (uint32_t)__cvta_generic_to_shared(Ws);

    auto issue = [&](int st, int k0) {
#pragma unroll
        for (int t = 0; t < 2; t++) {
            const int idx = tid + t * 256;
            const int m = idx >> 3, k4 = idx & 7;
            cp16(sA + (uint32_t)(((st * 64 + m) * LDT + k4 * 4) * 4),
                 A + (size_t)m * K + k0 + k4 * 4);
        }
        for (int idx = tid; idx < BN * 8; idx += 256) {
            const int n = idx >> 3, k4 = idx & 7;
            cp16(sW + (uint32_t)(((st * BN + n) * LDT + k4 * 4) * 4),
                 W + (size_t)(nBlock + n) * K + k0 + k4 * 4);
        }
    };

    const int nK = K / 32;
#pragma unroll
    for (int p = 0; p < S - 1; p++) {
        if (p < nK) issue(p, p * 32);
        cp_commit();
    }

    float acc[NT][4];
#pragma unroll
    for (int i = 0; i < NT; i++)
#pragma unroll
        for (int j = 0; j < 4; j++) acc[i][j] = 0.f;

    for (int kt = 0; kt < nK; kt++) {
        cp_wait<S - 2>();
        __syncthreads();
        const int pf = kt + S - 1;
        if (pf < nK) issue(pf % S, pf * 32);
        cp_commit();
        const float* a_ = As + (kt % S) * 64 * LDT;
        const float* w_ = Ws + (kt % S) * BN * LDT;
#pragma unroll
        for (int s = 0; s < 4; s++) {
            const int col = s * 8 + kk;
            const uint32_t a0 = tfb(a_[(wm * 16 + r) * LDT + col]);
            const uint32_t a1 = tfb(a_[(wm * 16 + r + 8) * LDT + col]);
            const uint32_t a2 = tfb(a_[(wm * 16 + r) * LDT + col + 4]);
            const uint32_t a3 = tfb(a_[(wm * 16 + r + 8) * LDT + col + 4]);
#pragma unroll
            for (int nt = 0; nt < NT; nt++) {
                const int n = wn * (BN / 2) + nt * 8 + r;
                mma8(acc[nt], a0, a1, a2, a3, tfb(w_[n * LDT + col]),
                     tfb(w_[n * LDT + col + 4]));
            }
        }
    }

    const int row0 = wm * 16 + r;
#pragma unroll
    for (int nt = 0; nt < NT; nt++) {
        const int col = nBlock + wn * (BN / 2) + nt * 8 + 2 * kk;
        const float b0v = bias[col], b1v = bias[col + 1];
        *reinterpret_cast<float2*>(out + (size_t)row0 * N + col) =
            make_float2(acc[nt][0] + b0v, acc[nt][1] + b1v);
        *reinterpret_cast<float2*>(out + (size_t)(row0 + 8) * N + col) =
            make_float2(acc[nt][2] + b0v, acc[nt][3] + b1v);
    }
}

// ---------------- persistent fused GRU chain v2 ----------------
// 64 blocks x 384 threads. Block owns 16 h-dims (48 gate rows) for all layers.
// Warps: wm = warp&3 (M 4x16), sec = warp>>2 (gate r/z/n), NT=2 (16 n per gate).
// Next-layer input sums computed in registers, ping-pong sum buffers.
__global__ __launch_bounds__(384) void gru_chain(
    const float* __restrict__ xe, float* __restrict__ nh, float* __restrict__ h1,
    const float* __restrict__ gru_Wih, const float* __restrict__ gru_bih,
    const float* __restrict__ gh, const float* __restrict__ hplus,
    float* __restrict__ sum0, float* __restrict__ sum1) {
    constexpr int S = 4;
    constexpr int LDT = 36;
    constexpr int K = EDIM;
    constexpr int CLD = 50;  // Cs row stride (48 + 2 pad)
    extern __shared__ float sm[];
    float* As = sm;                     // S*64*LDT
    float* Wsf = As + S * 64 * LDT;     // S*48*LDT
    float* Cs = Wsf + S * 48 * LDT;     // 64*CLD

    const int h0 = blockIdx.x * 16;
    const int tid = threadIdx.x, lane = tid & 31, warp = tid >> 5;
    const int wm = warp & 3, sec = warp >> 2;
    const int r = lane >> 2, kk = lane & 3;

    const uint32_t sA = (uint32_t)__cvta_generic_to_shared(As);
    const uint32_t sW = (uint32_t)__cvta_generic_to_shared(Wsf);

    float* sbuf[2] = {sum0, sum1};
    float prev[3];

    for (int layer = 0; layer < NLAYER; layer++) {
        const float* A;
        switch (layer) {
            case 0: A = xe; break;
            case 1: A = nh; break;
            case 2: A = nh + BH; break;
            default: A = sbuf[layer & 1]; break;
        }
        const float* Wih = gru_Wih + (size_t)layer * 3 * HDIM * K;
        const float* bih = gru_bih + (size_t)layer * 3 * HDIM;
        const float* ghL = gh + (size_t)layer * BATCH * 3 * HDIM;
        const float* hpL = hplus + (size_t)layer * BH;
        float* outh = nh + (size_t)layer * BH;
        float* sumNext = sbuf[(layer + 1) & 1];

        auto issue = [&](int st, int k0) {
#pragma unroll
            for (int t = 0; t < 2; t++) {
                const int idx = tid + t * 384;
                if (idx < 512) {
                    const int m = idx >> 3, k4 = idx & 7;
                    cp16(sA + (uint32_t)(((st * 64 + m) * LDT + k4 * 4) * 4),
                         A + (size_t)m * K + k0 + k4 * 4);
                }
            }
            {   // 48 rows x 8 k4 = 384 cp16
                const int wr = tid >> 3, k4 = tid & 7;
                const int grow = (wr >> 4) * HDIM + h0 + (wr & 15);
                cp16(sW + (uint32_t)(((st * 48 + wr) * LDT + k4 * 4) * 4),
                     Wih + (size_t)grow * K + k0 + k4 * 4);
            }
        };

        const int nK = K / 32;  // 32
#pragma unroll
        for (int p = 0; p < S - 1; p++) { issue(p, p * 32); cp_commit(); }

        float acc[2][4] = {{0.f, 0.f, 0.f, 0.f}, {0.f, 0.f, 0.f, 0.f}};
        for (int kt = 0; kt < nK; kt++) {
            cp_wait<S - 2>();
            __syncthreads();
            const int pf = kt + S - 1;
            if (pf < nK) issue(pf % S, pf * 32);
            cp_commit();
            const float* a_ = As + (kt % S) * 64 * LDT;
            const float* w_ = Wsf + (kt % S) * 48 * LDT;
#pragma unroll
            for (int s = 0; s < 4; s++) {
                const int col = s * 8 + kk;
                const uint32_t a0 = tfb(a_[(wm * 16 + r) * LDT + col]);
                const uint32_t a1 = tfb(a_[(wm * 16 + r + 8) * LDT + col]);
                const uint32_t a2 = tfb(a_[(wm * 16 + r) * LDT + col + 4]);
                const uint32_t a3 = tfb(a_[(wm * 16 + r + 8) * LDT + col + 4]);
#pragma unroll
                for (int nt = 0; nt < 2; nt++) {
                    const int brow = sec * 16 + nt * 8 + r;
                    mma8(acc[nt], a0, a1, a2, a3, tfb(w_[brow * LDT + col]),
                         tfb(w_[brow * LDT + col + 4]));
                }
            }
        }
        cp_wait<0>();

        const int row0 = wm * 16 + r;
#pragma unroll
        for (int nt = 0; nt < 2; nt++) {
            const int cl = sec * 16 + nt * 8 + 2 * kk;
            *reinterpret_cast<float2*>(&Cs[row0 * CLD + cl]) =
                make_float2(acc[nt][0], acc[nt][1]);
            *reinterpret_cast<float2*>(&Cs[(row0 + 8) * CLD + cl]) =
                make_float2(acc[nt][2], acc[nt][3]);
        }
        __syncthreads();

        int t = 0;
        for (int idx = tid; idx < 1024; idx += 384, t++) {
            const int b = idx >> 4, hh = idx & 15;
            const int h = h0 + hh;
            const float ir = Cs[b * CLD + hh] + bih[h];
            const float iz = Cs[b * CLD + 16 + hh] + bih[HDIM + h];
            const float in_ = Cs[b * CLD + 32 + hh] + bih[2 * HDIM + h];
            const float* ghb = ghL + (size_t)b * 3 * HDIM + h;
            const float rr = 1.f / (1.f + expf(-(ir + ghb[0])));
            const float zz = 1.f / (1.f + expf(-(iz + ghb[HDIM])));
            const float nn = tanhf(in_ + rr * ghb[2 * HDIM]);
            const float hp = hpL[(size_t)b * HDIM + h];
            const float o = (1.f - zz) * nn + zz * hp;
            outh[(size_t)b * HDIM + h] = o;
            if (layer == 0) h1[(size_t)b * HDIM + h] = o;
            if (layer >= 2 && layer <= 6)
                sumNext[(size_t)b * HDIM + h] = o + prev[t];
            prev[t] = o;
        }

        if (layer < NLAYER - 1) {
            __threadfence();
            __syncthreads();
            if (tid == 0) {
                atomicAdd(&g_bar[layer], 1);
                while (atomicAdd(&g_bar[layer], 0) < (int)gridDim.x) __nanosleep(32);
            }
            __syncthreads();
        }
    }
}

// ---------------- 2-pass online log_softmax ----------------
__global__ __launch_bounds__(1024) void log_softmax_kernel(float* __restrict__ logits) {
    const int b = blockIdx.x;
    float* row = logits + (size_t)b * VDIM;
    __shared__ float smax[32], ssum[32];
    __shared__ float s_lse;
    const int lane = threadIdx.x & 31;
    const int wid = threadIdx.x >> 5;

    float m = -1e30f, s = 0.f;
    const float4* r4 = reinterpret_cast<const float4*>(row);
    for (int v = threadIdx.x; v < VDIM / 4; v += blockDim.x) {
        float4 x = r4[v];
#define ONE(val) { float d = (val) - m; \
        if (d > 0.f) { s = s * __expf(-d) + 1.f; m = (val); } else s += __expf(d); }
        ONE(x.x) ONE(x.y) ONE(x.z) ONE(x.w)
#undef ONE
    }
#pragma unroll
    for (int o = 16; o; o >>= 1) {
        float mo = __shfl_xor_sync(0xffffffffu, m, o);
        float so = __shfl_xor_sync(0xffffffffu, s, o);
        float mn = fmaxf(m, mo);
        s = s * __expf(m - mn) + so * __expf(mo - mn);
        m = mn;
    }
    if (lane == 0) { smax[wid] = m; ssum[wid] = s; }
    __syncthreads();
    if (wid == 0) {
        float mm = (lane < (blockDim.x >> 5)) ? smax[lane] : -1e30f;
        float ss = (lane < (blockDim.x >> 5)) ? ssum[lane] : 0.f;
#pragma unroll
        for (int o = 16; o; o >>= 1) {
            float mo = __shfl_xor_sync(0xffffffffu, mm, o);
            float so = __shfl_xor_sync(0xffffffffu, ss, o);
            float mn = fmaxf(mm, mo);
            ss = ss * __expf(mm - mn) + so * __expf(mo - mn);
            mm = mn;
        }
        if (lane == 0) s_lse = mm + logf(ss);
    }
    __syncthreads();
    const float lse = s_lse;
    float4* w4 = reinterpret_cast<float4*>(row);
    for (int v = threadIdx.x; v < VDIM / 4; v += blockDim.x) {
        float4 x = w4[v];
        x.x -= lse; x.y -= lse; x.z -= lse; x.w -= lse;
        w4[v] = x;
    }
}

// ---------------- launch ----------------
extern "C" void kernel_launch(void* const* d_in, const int* in_sizes, int n_in,
                              void* d_out, int out_size) {
    const float* feature   = (const float*)d_in[0];
    const int*   x         = (const int*)d_in[1];
    const float* attention = (const float*)d_in[2];
    const float* hiddens   = (const float*)d_in[3];
    const float* emb       = (const float*)d_in[4];
    const float* map_W     = (const float*)d_in[5];
    const float* map_b     = (const float*)d_in[6];
    const float* ai_W      = (const float*)d_in[7];
    const float* ai_b      = (const float*)d_in[8];
    const float* ah_W      = (const float*)d_in[9];
    const float* ah_b      = (const float*)d_in[10];
    const float* ao_W      = (const float*)d_in[11];
    const float* ao_b      = (const float*)d_in[12];
    const float* gru_Wih   = (const float*)d_in[13];
    const float* gru_Whh   = (const float*)d_in[14];
    const float* gru_bih   = (const float*)d_in[15];
    const float* gru_bhh   = (const float*)d_in[16];
    const float* out_W     = (const float*)d_in[17];
    const float* out_b     = (const float*)d_in[18];

    float* out = (float*)d_out;
    float* logp = out;
    float* h1   = out + (size_t)BATCH * VDIM;
    float* nh   = h1 + (size_t)BATCH * HDIM;

    float *xe, *buf0, *buf1, *gh, *hplus, *sum0, *sum1;
    cudaGetSymbolAddress((void**)&xe, g_xe);
    cudaGetSymbolAddress((void**)&buf0, g_buf0);
    cudaGetSymbolAddress((void**)&buf1, g_buf1);
    cudaGetSymbolAddress((void**)&gh, g_gh);
    cudaGetSymbolAddress((void**)&hplus, g_hplus);
    cudaGetSymbolAddress((void**)&sum0, g_sum0);
    cudaGetSymbolAddress((void**)&sum1, g_sum1);

    const int SM_G64 = (3 * 64 * 36 * 2) * 4;                           // 55296
    const int SM_CH  = (4 * 64 * 36 + 4 * 48 * 36) * 4 + 64 * 50 * 4;   // 77312
    cudaFuncSetAttribute((const void*)gemm_pipe<64>,
                         cudaFuncAttributeMaxDynamicSharedMemorySize, SM_G64);
    cudaFuncSetAttribute((const void*)gru_chain,
                         cudaFuncAttributeMaxDynamicSharedMemorySize, SM_CH);

    // 1) embed (+ barrier init)
    embed_relu_kernel<<<BATCH, 256>>>(emb, x, xe);

    // 2) persistent attention chain; final epilogue writes hplus[l] = hiddens[l]+attn
    attn_chain<<<HDIM / 16, 256>>>(feature, attention, map_W, map_b, ai_W, ai_b,
                                   ah_W, ah_b, ao_W, ao_b, buf0, buf1,
                                   hiddens, hplus);

    // 3) all 8 gh GEMMs, one batched launch: gh[l] = hplus[l] @ Whh[l]^T + bhh[l]
    gemm_pipe<64><<<dim3(3 * HDIM / 64, NLAYER, 1), 256, SM_G64>>>(
        hplus, gru_Whh, gru_bhh, gh, HDIM, 3 * HDIM, BH);

    // 4) fused persistent GRU chain (all 8 layers, 1 launch, 64 blocks)
    gru_chain<<<HDIM / 16, 384, SM_CH>>>(xe, nh, h1, gru_Wih, gru_bih, gh,
                                         hplus, sum0, sum1);

    // 5) output projection + log-softmax
    gemm_pipe<64><<<dim3(VDIM / 64, 1, 1), 256, SM_G64>>>(
        nh + 7 * (size_t)BH, out_W, out_b, logp, HDIM, VDIM, 0);
    log_softmax_kernel<<<BATCH, 1024>>>(logp);
}

// round 7
// speedup vs baseline: 1.3383x; 1.1392x over previous
#include <cuda_runtime.h>
#include <math.h>
#include <stdint.h>

#define BATCH 64
#define EDIM 1024
#define HDIM 1024
#define FDIM 2048
#define VDIM 32000
#define NLAYER 8
#define BH (BATCH * HDIM)

// ---------------- scratch (no allocation allowed) ----------------
__device__ __align__(16) float g_xe[BATCH * EDIM];
__device__ __align__(16) float g_buf0[BATCH * HDIM];
__device__ __align__(16) float g_buf1[BATCH * HDIM];
__device__ __align__(16) float g_gh[NLAYER * BATCH * 3 * HDIM];
__device__ __align__(16) float g_hplus[NLAYER * BATCH * HDIM];
__device__ __align__(16) float g_sum0[BATCH * HDIM];
__device__ __align__(16) float g_sum1[BATCH * HDIM];
__device__ __align__(16) float g_part[64 * BATCH * 48];   // split-K partials per group
__device__ int g_bar[NLAYER];    // gru chain barriers
__device__ int g_bar2[4];        // attn chain barriers
__device__ int g_flag[64];       // split-K ready flags per group

// ---------------- ptx helpers ----------------
__device__ __forceinline__ uint32_t tfb(float x) { return __float_as_uint(x); }

__device__ __forceinline__ void cp16(uint32_t saddr, const void* g) {
    asm volatile("cp.async.cg.shared.global [%0], [%1], 16;\n" ::"r"(saddr), "l"(g));
}
__device__ __forceinline__ void cp_commit() { asm volatile("cp.async.commit_group;\n"); }
template <int N>
__device__ __forceinline__ void cp_wait() { asm volatile("cp.async.wait_group %0;\n" ::"n"(N)); }

__device__ __forceinline__ void mma8(float* c, uint32_t a0, uint32_t a1, uint32_t a2,
                                     uint32_t a3, uint32_t b0, uint32_t b1) {
    asm volatile(
        "mma.sync.aligned.m16n8k8.row.col.f32.tf32.tf32.f32 "
        "{%0,%1,%2,%3}, {%4,%5,%6,%7}, {%8,%9}, {%0,%1,%2,%3};\n"
        : "+f"(c[0]), "+f"(c[1]), "+f"(c[2]), "+f"(c[3])
        : "r"(a0), "r"(a1), "r"(a2), "r"(a3), "r"(b0), "r"(b1));
}

// ---------------- embed + barrier init ----------------
__global__ void embed_relu_kernel(const float* __restrict__ emb,
                                  const int* __restrict__ x,
                                  float* __restrict__ xe) {
    if (blockIdx.x == 0) {
        const int t = threadIdx.x;
        if (t < NLAYER) g_bar[t] = 0;
        else if (t < NLAYER + 4) g_bar2[t - NLAYER] = 0;
        else if (t >= 16 && t < 80) g_flag[t - 16] = 0;
    }
    const int b = blockIdx.x;
    const int row = x[b];
    const float* src = emb + (size_t)row * EDIM;
    float* dst = xe + (size_t)b * EDIM;
    for (int e = threadIdx.x; e < EDIM; e += blockDim.x) {
        float v = src[e];
        dst[e] = v > 0.f ? v : 0.f;
    }
}

// ---------------- persistent attention chain (4 layers, 64 blocks) ----------------
__global__ __launch_bounds__(256) void attn_chain(
    const float* __restrict__ feature, const float* __restrict__ attention,
    const float* __restrict__ mapW, const float* __restrict__ mapb,
    const float* __restrict__ aiW, const float* __restrict__ aib,
    const float* __restrict__ ahW, const float* __restrict__ ahb,
    const float* __restrict__ aoW, const float* __restrict__ aob,
    float* __restrict__ buf0, float* __restrict__ buf1,
    const float* __restrict__ hiddens, float* __restrict__ hplus) {
    constexpr int S = 3, LDT = 36, BN = 16;
    __shared__ float As[S * 64 * LDT];
    __shared__ float Ws[S * BN * LDT];

    const float* Aptr[4] = {feature, buf0, buf1, buf0};
    const float* Wptr[4] = {mapW, aiW, ahW, aoW};
    const float* bptr[4] = {mapb, aib, ahb, aob};
    float* optr[3] = {buf0, buf1, buf0};
    const int Ks[4] = {FDIM, HDIM, HDIM, HDIM};

    const int tid = threadIdx.x, lane = tid & 31, warp = tid >> 5;
    const int wm = warp & 3, wn = warp >> 2;
    const int r = lane >> 2, kk = lane & 3;
    const int nBlock = blockIdx.x * BN;

    const uint32_t sA = (uint32_t)__cvta_generic_to_shared(As);
    const uint32_t sW = (uint32_t)__cvta_generic_to_shared(Ws);

    for (int layer = 0; layer < 4; layer++) {
        const float* A = Aptr[layer];
        const float* W = Wptr[layer];
        const int K = Ks[layer];
        const int nK = K / 32;

        auto issue = [&](int st, int k0) {
#pragma unroll
            for (int t = 0; t < 2; t++) {
                const int idx = tid + t * 256;
                const int m = idx >> 3, k4 = idx & 7;
                cp16(sA + (uint32_t)(((st * 64 + m) * LDT + k4 * 4) * 4),
                     A + (size_t)m * K + k0 + k4 * 4);
            }
            if (tid < BN * 8) {
                const int wr = tid >> 3, k4 = tid & 7;
                cp16(sW + (uint32_t)(((st * BN + wr) * LDT + k4 * 4) * 4),
                     W + (size_t)(nBlock + wr) * K + k0 + k4 * 4);
            }
        };

#pragma unroll
        for (int p = 0; p < S - 1; p++) {
            if (p < nK) issue(p, p * 32);
            cp_commit();
        }

        float acc[4] = {0.f, 0.f, 0.f, 0.f};
        for (int kt = 0; kt < nK; kt++) {
            cp_wait<S - 2>();
            __syncthreads();
            const int pf = kt + S - 1;
            if (pf < nK) issue(pf % S, pf * 32);
            cp_commit();
            const float* a_ = As + (kt % S) * 64 * LDT;
            const float* w_ = Ws + (kt % S) * BN * LDT;
#pragma unroll
            for (int s = 0; s < 4; s++) {
                const int col = s * 8 + kk;
                const uint32_t a0 = tfb(a_[(wm * 16 + r) * LDT + col]);
                const uint32_t a1 = tfb(a_[(wm * 16 + r + 8) * LDT + col]);
                const uint32_t a2 = tfb(a_[(wm * 16 + r) * LDT + col + 4]);
                const uint32_t a3 = tfb(a_[(wm * 16 + r + 8) * LDT + col + 4]);
                const int n = wn * 8 + r;
                mma8(acc, a0, a1, a2, a3, tfb(w_[n * LDT + col]),
                     tfb(w_[n * LDT + col + 4]));
            }
        }
        cp_wait<0>();

        const int row0 = wm * 16 + r;
        const int col = nBlock + wn * 8 + 2 * kk;
        const float b0v = bptr[layer][col], b1v = bptr[layer][col + 1];
        float v0 = fmaxf(acc[0] + b0v, 0.f), v1 = fmaxf(acc[1] + b1v, 0.f);
        float v2 = fmaxf(acc[2] + b0v, 0.f), v3 = fmaxf(acc[3] + b1v, 0.f);
        if (layer == 0) {
            v0 += attention[(size_t)row0 * HDIM + col];
            v1 += attention[(size_t)row0 * HDIM + col + 1];
            v2 += attention[(size_t)(row0 + 8) * HDIM + col];
            v3 += attention[(size_t)(row0 + 8) * HDIM + col + 1];
        }
        if (layer < 3) {
            float* o = optr[layer];
            *reinterpret_cast<float2*>(o + (size_t)row0 * HDIM + col) = make_float2(v0, v1);
            *reinterpret_cast<float2*>(o + (size_t)(row0 + 8) * HDIM + col) = make_float2(v2, v3);
        } else {
#pragma unroll
            for (int l = 0; l < NLAYER; l++) {
                const size_t b0i = (size_t)l * BH + (size_t)row0 * HDIM + col;
                const size_t b1i = (size_t)l * BH + (size_t)(row0 + 8) * HDIM + col;
                float2 h0 = *reinterpret_cast<const float2*>(hiddens + b0i);
                float2 h8 = *reinterpret_cast<const float2*>(hiddens + b1i);
                *reinterpret_cast<float2*>(hplus + b0i) = make_float2(h0.x + v0, h0.y + v1);
                *reinterpret_cast<float2*>(hplus + b1i) = make_float2(h8.x + v2, h8.y + v3);
            }
        }

        if (layer < 3) {
            __threadfence();
            __syncthreads();
            if (tid == 0) {
                atomicAdd(&g_bar2[layer], 1);
                while (atomicAdd(&g_bar2[layer], 0) < (int)gridDim.x) __nanosleep(32);
            }
            __syncthreads();
        }
    }
}

// ---------------- pipelined tf32 GEMM: C[64,N] = A @ W^T + bias ----------------
template <int BN>
__global__ __launch_bounds__(256) void gemm_pipe(
    const float* __restrict__ A, const float* __restrict__ W,
    const float* __restrict__ bias, float* __restrict__ out,
    int K, int N, int strideA) {
    constexpr int S = 3;
    constexpr int LDT = 36;
    constexpr int NT = BN / 16;
    extern __shared__ float sm[];
    float* As = sm;
    float* Ws = sm + S * 64 * LDT;

    const int y = blockIdx.y;
    A += (size_t)y * strideA;
    W += (size_t)y * N * K;
    bias += (size_t)y * N;
    out += (size_t)y * BATCH * N;

    const int tid = threadIdx.x, lane = tid & 31, warp = tid >> 5;
    const int wm = warp & 3, wn = warp >> 2;
    const int nBlock = blockIdx.x * BN;
    const int r = lane >> 2, kk = lane & 3;

    const uint32_t sA = (uint32_t)__cvta_generic_to_shared(As);
    const uint32_t sW = (uint32_t)__cvta_generic_to_shared(Ws);

    auto issue = [&](int st, int k0) {
#pragma unroll
        for (int t = 0; t < 2; t++) {
            const int idx = tid + t * 256;
            const int m = idx >> 3, k4 = idx & 7;
            cp16(sA + (uint32_t)(((st * 64 + m) * LDT + k4 * 4) * 4),
                 A + (size_t)m * K + k0 + k4 * 4);
        }
        for (int idx = tid; idx < BN * 8; idx += 256) {
            const int n = idx >> 3, k4 = idx & 7;
            cp16(sW + (uint32_t)(((st * BN + n) * LDT + k4 * 4) * 4),
                 W + (size_t)(nBlock + n) * K + k0 + k4 * 4);
        }
    };

    const int nK = K / 32;
#pragma unroll
    for (int p = 0; p < S - 1; p++) {
        if (p < nK) issue(p, p * 32);
        cp_commit();
    }

    float acc[NT][4];
#pragma unroll
    for (int i = 0; i < NT; i++)
#pragma unroll
        for (int j = 0; j < 4; j++) acc[i][j] = 0.f;

    for (int kt = 0; kt < nK; kt++) {
        cp_wait<S - 2>();
        __syncthreads();
        const int pf = kt + S - 1;
        if (pf < nK) issue(pf % S, pf * 32);
        cp_commit();
        const float* a_ = As + (kt % S) * 64 * LDT;
        const float* w_ = Ws + (kt % S) * BN * LDT;
#pragma unroll
        for (int s = 0; s < 4; s++) {
            const int col = s * 8 + kk;
            const uint32_t a0 = tfb(a_[(wm * 16 + r) * LDT + col]);
            const uint32_t a1 = tfb(a_[(wm * 16 + r + 8) * LDT + col]);
            const uint32_t a2 = tfb(a_[(wm * 16 + r) * LDT + col + 4]);
            const uint32_t a3 = tfb(a_[(wm * 16 + r + 8) * LDT + col + 4]);
#pragma unroll
            for (int nt = 0; nt < NT; nt++) {
                const int n = wn * (BN / 2) + nt * 8 + r;
                mma8(acc[nt], a0, a1, a2, a3, tfb(w_[n * LDT + col]),
                     tfb(w_[n * LDT + col + 4]));
            }
        }
    }

    const int row0 = wm * 16 + r;
#pragma unroll
    for (int nt = 0; nt < NT; nt++) {
        const int col = nBlock + wn * (BN / 2) + nt * 8 + 2 * kk;
        const float b0v = bias[col], b1v = bias[col + 1];
        *reinterpret_cast<float2*>(out + (size_t)row0 * N + col) =
            make_float2(acc[nt][0] + b0v, acc[nt][1] + b1v);
        *reinterpret_cast<float2*>(out + (size_t)(row0 + 8) * N + col) =
            make_float2(acc[nt][2] + b0v, acc[nt][3] + b1v);
    }
}

// ---------------- persistent fused GRU chain v3: split-K over 128 CTAs ----------------
// blockIdx.x: bit0 = K-half (z), bits1+ = h-group g (16 h-dims, 48 gate rows).
// z=1 computes K[512:1024) partials -> g_part + flag; z=0 computes K[0:512),
// combines, and runs the gate epilogue. Global barrier between layers.
__global__ __launch_bounds__(384) void gru_chain(
    const float* __restrict__ xe, float* __restrict__ nh, float* __restrict__ h1,
    const float* __restrict__ gru_Wih, const float* __restrict__ gru_bih,
    const float* __restrict__ gh, const float* __restrict__ hplus,
    float* __restrict__ sum0, float* __restrict__ sum1) {
    constexpr int S = 4;
    constexpr int LDT = 36;
    constexpr int K = EDIM;
    constexpr int KH = K / 2;       // 512 per half
    constexpr int CLD = 50;
    extern __shared__ float sm[];
    float* As = sm;                  // S*64*LDT
    float* Wsf = As + S * 64 * LDT;  // S*48*LDT
    float* Cs = Wsf + S * 48 * LDT;  // 64*CLD

    const int g = blockIdx.x >> 1;
    const int z = blockIdx.x & 1;
    const int h0 = g * 16;
    const int kBase = z * KH;
    const int tid = threadIdx.x, lane = tid & 31, warp = tid >> 5;
    const int wm = warp & 3, sec = warp >> 2;
    const int r = lane >> 2, kk = lane & 3;

    const uint32_t sA = (uint32_t)__cvta_generic_to_shared(As);
    const uint32_t sW = (uint32_t)__cvta_generic_to_shared(Wsf);

    float* sbuf[2] = {sum0, sum1};
    float prev[3];

    for (int layer = 0; layer < NLAYER; layer++) {
        const float* A;
        switch (layer) {
            case 0: A = xe; break;
            case 1: A = nh; break;
            case 2: A = nh + BH; break;
            default: A = sbuf[layer & 1]; break;
        }
        const float* Wih = gru_Wih + (size_t)layer * 3 * HDIM * K;
        const float* bih = gru_bih + (size_t)layer * 3 * HDIM;
        const float* ghL = gh + (size_t)layer * BATCH * 3 * HDIM;
        const float* hpL = hplus + (size_t)layer * BH;
        float* outh = nh + (size_t)layer * BH;
        float* sumNext = sbuf[(layer + 1) & 1];

        auto issue = [&](int st, int k0) {
#pragma unroll
            for (int t = 0; t < 2; t++) {
                const int idx = tid + t * 384;
                if (idx < 512) {
                    const int m = idx >> 3, k4 = idx & 7;
                    cp16(sA + (uint32_t)(((st * 64 + m) * LDT + k4 * 4) * 4),
                         A + (size_t)m * K + k0 + k4 * 4);
                }
            }
            {
                const int wr = tid >> 3, k4 = tid & 7;
                const int grow = (wr >> 4) * HDIM + h0 + (wr & 15);
                cp16(sW + (uint32_t)(((st * 48 + wr) * LDT + k4 * 4) * 4),
                     Wih + (size_t)grow * K + k0 + k4 * 4);
            }
        };

        const int nK = KH / 32;  // 16
#pragma unroll
        for (int p = 0; p < S - 1; p++) { issue(p, kBase + p * 32); cp_commit(); }

        float acc[2][4] = {{0.f, 0.f, 0.f, 0.f}, {0.f, 0.f, 0.f, 0.f}};
        for (int kt = 0; kt < nK; kt++) {
            cp_wait<S - 2>();
            __syncthreads();
            const int pf = kt + S - 1;
            if (pf < nK) issue(pf % S, kBase + pf * 32);
            cp_commit();
            const float* a_ = As + (kt % S) * 64 * LDT;
            const float* w_ = Wsf + (kt % S) * 48 * LDT;
#pragma unroll
            for (int s = 0; s < 4; s++) {
                const int col = s * 8 + kk;
                const uint32_t a0 = tfb(a_[(wm * 16 + r) * LDT + col]);
                const uint32_t a1 = tfb(a_[(wm * 16 + r + 8) * LDT + col]);
                const uint32_t a2 = tfb(a_[(wm * 16 + r) * LDT + col + 4]);
                const uint32_t a3 = tfb(a_[(wm * 16 + r + 8) * LDT + col + 4]);
#pragma unroll
                for (int nt = 0; nt < 2; nt++) {
                    const int brow = sec * 16 + nt * 8 + r;
                    mma8(acc[nt], a0, a1, a2, a3, tfb(w_[brow * LDT + col]),
                         tfb(w_[brow * LDT + col + 4]));
                }
            }
        }
        cp_wait<0>();

        const int row0 = wm * 16 + r;

        if (z == 1) {
            // publish partials, raise flag
            float* pg = g_part + (size_t)g * BATCH * 48;
#pragma unroll
            for (int nt = 0; nt < 2; nt++) {
                const int cl = sec * 16 + nt * 8 + 2 * kk;
                *reinterpret_cast<float2*>(pg + row0 * 48 + cl) =
                    make_float2(acc[nt][0], acc[nt][1]);
                *reinterpret_cast<float2*>(pg + (row0 + 8) * 48 + cl) =
                    make_float2(acc[nt][2], acc[nt][3]);
            }
            __threadfence();
            __syncthreads();
            if (tid == 0) atomicExch(&g_flag[g], layer + 1);
        } else {
            // wait for partner partials, combine, epilogue
            if (tid == 0) {
                while (atomicAdd(&g_flag[g], 0) < layer + 1) __nanosleep(32);
            }
            __syncthreads();
            const float* pg = g_part + (size_t)g * BATCH * 48;
#pragma unroll
            for (int nt = 0; nt < 2; nt++) {
                const int cl = sec * 16 + nt * 8 + 2 * kk;
                float2 p0 = *reinterpret_cast<const float2*>(pg + row0 * 48 + cl);
                float2 p8 = *reinterpret_cast<const float2*>(pg + (row0 + 8) * 48 + cl);
                *reinterpret_cast<float2*>(&Cs[row0 * CLD + cl]) =
                    make_float2(acc[nt][0] + p0.x, acc[nt][1] + p0.y);
                *reinterpret_cast<float2*>(&Cs[(row0 + 8) * CLD + cl]) =
                    make_float2(acc[nt][2] + p8.x, acc[nt][3] + p8.y);
            }
            __syncthreads();

            int t = 0;
            for (int idx = tid; idx < 1024; idx += 384, t++) {
                const int b = idx >> 4, hh = idx & 15;
                const int h = h0 + hh;
                const float ir = Cs[b * CLD + hh] + bih[h];
                const float iz = Cs[b * CLD + 16 + hh] + bih[HDIM + h];
                const float in_ = Cs[b * CLD + 32 + hh] + bih[2 * HDIM + h];
                const float* ghb = ghL + (size_t)b * 3 * HDIM + h;
                const float rr = 1.f / (1.f + expf(-(ir + ghb[0])));
                const float zz = 1.f / (1.f + expf(-(iz + ghb[HDIM])));
                const float nn = tanhf(in_ + rr * ghb[2 * HDIM]);
                const float hp = hpL[(size_t)b * HDIM + h];
                const float o = (1.f - zz) * nn + zz * hp;
                outh[(size_t)b * HDIM + h] = o;
                if (layer == 0) h1[(size_t)b * HDIM + h] = o;
                if (layer >= 2 && layer <= 6)
                    sumNext[(size_t)b * HDIM + h] = o + prev[t];
                prev[t] = o;
            }
        }

        if (layer < NLAYER - 1) {
            __threadfence();
            __syncthreads();
            if (tid == 0) {
                atomicAdd(&g_bar[layer], 1);
                while (atomicAdd(&g_bar[layer], 0) < (int)gridDim.x) __nanosleep(32);
            }
            __syncthreads();
        }
    }
}

// ---------------- 2-pass online log_softmax ----------------
__global__ __launch_bounds__(1024) void log_softmax_kernel(float* __restrict__ logits) {
    const int b = blockIdx.x;
    float* row = logits + (size_t)b * VDIM;
    __shared__ float smax[32], ssum[32];
    __shared__ float s_lse;
    const int lane = threadIdx.x & 31;
    const int wid = threadIdx.x >> 5;

    float m = -1e30f, s = 0.f;
    const float4* r4 = reinterpret_cast<const float4*>(row);
    for (int v = threadIdx.x; v < VDIM / 4; v += blockDim.x) {
        float4 x = r4[v];
#define ONE(val) { float d = (val) - m; \
        if (d > 0.f) { s = s * __expf(-d) + 1.f; m = (val); } else s += __expf(d); }
        ONE(x.x) ONE(x.y) ONE(x.z) ONE(x.w)
#undef ONE
    }
#pragma unroll
    for (int o = 16; o; o >>= 1) {
        float mo = __shfl_xor_sync(0xffffffffu, m, o);
        float so = __shfl_xor_sync(0xffffffffu, s, o);
        float mn = fmaxf(m, mo);
        s = s * __expf(m - mn) + so * __expf(mo - mn);
        m = mn;
    }
    if (lane == 0) { smax[wid] = m; ssum[wid] = s; }
    __syncthreads();
    if (wid == 0) {
        float mm = (lane < (blockDim.x >> 5)) ? smax[lane] : -1e30f;
        float ss = (lane < (blockDim.x >> 5)) ? ssum[lane] : 0.f;
#pragma unroll
        for (int o = 16; o; o >>= 1) {
            float mo = __shfl_xor_sync(0xffffffffu, mm, o);
            float so = __shfl_xor_sync(0xffffffffu, ss, o);
            float mn = fmaxf(mm, mo);
            ss = ss * __expf(mm - mn) + so * __expf(mo - mn);
            mm = mn;
        }
        if (lane == 0) s_lse = mm + logf(ss);
    }
    __syncthreads();
    const float lse = s_lse;
    float4* w4 = reinterpret_cast<float4*>(row);
    for (int v = threadIdx.x; v < VDIM / 4; v += blockDim.x) {
        float4 x = w4[v];
        x.x -= lse; x.y -= lse; x.z -= lse; x.w -= lse;
        w4[v] = x;
    }
}

// ---------------- launch ----------------
extern "C" void kernel_launch(void* const* d_in, const int* in_sizes, int n_in,
                              void* d_out, int out_size) {
    const float* feature   = (const float*)d_in[0];
    const int*   x         = (const int*)d_in[1];
    const float* attention = (const float*)d_in[2];
    const float* hiddens   = (const float*)d_in[3];
    const float* emb       = (const float*)d_in[4];
    const float* map_W     = (const float*)d_in[5];
    const float* map_b     = (const float*)d_in[6];
    const float* ai_W      = (const float*)d_in[7];
    const float* ai_b      = (const float*)d_in[8];
    const float* ah_W      = (const float*)d_in[9];
    const float* ah_b      = (const float*)d_in[10];
    const float* ao_W      = (const float*)d_in[11];
    const float* ao_b      = (const float*)d_in[12];
    const float* gru_Wih   = (const float*)d_in[13];
    const float* gru_Whh   = (const float*)d_in[14];
    const float* gru_bih   = (const float*)d_in[15];
    const float* gru_bhh   = (const float*)d_in[16];
    const float* out_W     = (const float*)d_in[17];
    const float* out_b     = (const float*)d_in[18];

    float* out = (float*)d_out;
    float* logp = out;
    float* h1   = out + (size_t)BATCH * VDIM;
    float* nh   = h1 + (size_t)BATCH * HDIM;

    float *xe, *buf0, *buf1, *gh, *hplus, *sum0, *sum1;
    cudaGetSymbolAddress((void**)&xe, g_xe);
    cudaGetSymbolAddress((void**)&buf0, g_buf0);
    cudaGetSymbolAddress((void**)&buf1, g_buf1);
    cudaGetSymbolAddress((void**)&gh, g_gh);
    cudaGetSymbolAddress((void**)&hplus, g_hplus);
    cudaGetSymbolAddress((void**)&sum0, g_sum0);
    cudaGetSymbolAddress((void**)&sum1, g_sum1);

    const int SM_G128 = (3 * 64 * 36 + 3 * 128 * 36) * 4;               // 82944
    const int SM_CH   = (4 * 64 * 36 + 4 * 48 * 36) * 4 + 64 * 50 * 4;  // 77312
    cudaFuncSetAttribute((const void*)gemm_pipe<128>,
                         cudaFuncAttributeMaxDynamicSharedMemorySize, SM_G128);
    cudaFuncSetAttribute((const void*)gru_chain,
                         cudaFuncAttributeMaxDynamicSharedMemorySize, SM_CH);

    // 1) embed (+ barrier/flag init)
    embed_relu_kernel<<<BATCH, 256>>>(emb, x, xe);

    // 2) persistent attention chain; final epilogue writes hplus
    attn_chain<<<HDIM / 16, 256>>>(feature, attention, map_W, map_b, ai_W, ai_b,
                                   ah_W, ah_b, ao_W, ao_b, buf0, buf1,
                                   hiddens, hplus);

    // 3) all 8 gh GEMMs, one batched launch (BN=128 -> 192 CTAs)
    gemm_pipe<128><<<dim3(3 * HDIM / 128, NLAYER, 1), 256, SM_G128>>>(
        hplus, gru_Whh, gru_bhh, gh, HDIM, 3 * HDIM, BH);

    // 4) fused persistent GRU chain (128 CTAs: 64 groups x 2 K-halves)
    gru_chain<<<128, 384, SM_CH>>>(xe, nh, h1, gru_Wih, gru_bih, gh,
                                   hplus, sum0, sum1);

    // 5) output projection (BN=128 -> 250 CTAs) + log-softmax
    gemm_pipe<128><<<dim3(VDIM / 128, 1, 1), 256, SM_G128>>>(
        nh + 7 * (size_t)BH, out_W, out_b, logp, HDIM, VDIM, 0);
    log_softmax_kernel<<<BATCH, 1024>>>(logp);
}